// round 6
// baseline (speedup 1.0000x reference)
#include <cuda_runtime.h>
#include <cuda_bf16.h>
#include <cstddef>

#define Bc 4
#define Hc 8
#define Pc 32
#define Nc 32
#define Dc 16
#define Lc 1024
#define WINc 10
#define NFc 6
#define PREDc 96
#define SEQc 512
#define EPSc 1.1920929e-07f
#define LOG2E 1.4426950408889634f

__device__ float g_h0[Bc * Hc * Lc * Dc];
__device__ float g_h1[Bc * Hc * Lc * Dc];

typedef unsigned long long u64;

__device__ __forceinline__ void ffma2(u64 &d, u64 a, u64 b, u64 c) {
    asm("fma.rn.f32x2 %0, %1, %2, %3;" : "=l"(d) : "l"(a), "l"(b), "l"(c));
}
__device__ __forceinline__ u64 pack2(float lo, float hi) {
    u64 r; asm("mov.b64 %0, {%1, %2};" : "=l"(r) : "f"(lo), "f"(hi)); return r;
}
__device__ __forceinline__ void unpack2(u64 v, float &lo, float &hi) {
    asm("mov.b64 {%0, %1}, %2;" : "=f"(lo), "=f"(hi) : "l"(v));
}
__device__ __forceinline__ float ex2(float x) {
    float r; asm("ex2.approx.f32 %0, %1;" : "=f"(r) : "f"(x)); return r;
}
__device__ __forceinline__ float gelu_exact(float x) {
    return 0.5f * x * (1.0f + erff(x * 0.70710678118654752f));
}

// ---------------------------------------------------------------------------
// Fused layer: signed banded attention + residual + RMSNorm + conv-FFN
// + residual + RMSNorm. Block per (p,h,b); 256 thr = 8 warps; lane = query.
// Keys staged in smem once (coalesced); compute reads are uniform broadcast
// LDS (29cy). Two-pass softmax: pass1 z-sums only, pass2 single combined
// accumulator -> fewer regs, smaller partial buffer (reuses key smem).
// ---------------------------------------------------------------------------
__global__ __launch_bounds__(256) void attn_ffn_kernel(
    const float* __restrict__ in, float* __restrict__ out,
    const float* __restrict__ log_scale, const float* __restrict__ attn_nw,
    const float* __restrict__ up_w, const float* __restrict__ down_w,
    const float* __restrict__ ffn_nw)
{
    __shared__ float sk[288 * 16];        // keys; later reused for acc partials
    __shared__ float zpart[8][2][32];     // per-warp (zp, zn) per query

    const int p    = blockIdx.x;
    const int hh   = blockIdx.y;
    const int b    = blockIdx.z;
    const int tid  = threadIdx.x;
    const int warp = tid >> 5, lane = tid & 31;

    const float* base = in + ((size_t)(b * Hc + hh) * Lc) * Dc;
    const float* qb   = base + (size_t)p * Nc * Dc;
    const int npat = min(WINc - 1, (Pc - 1) - p);
    const int nk   = npat * Nc;

    const float scale = fminf(fmaxf(__expf(log_scale[0]), 1.0f), 30.0f) * 0.25f;
    const float c = scale * LOG2E;

    // stage keys (coalesced float4, high MLP)
    {
        const float4* kb4 = (const float4*)(base + (size_t)(p + 1) * Nc * Dc);
        float4* sk4 = (float4*)sk;
        for (int i = tid; i < nk * 4; i += 256) sk4[i] = kb4[i];
    }

    // lane's query, pre-scaled+packed
    u64 q2[8];
    {
        const float4* q4 = (const float4*)(qb + (size_t)lane * Dc);
        float4 a = q4[0], b4 = q4[1], cc = q4[2], d4 = q4[3];
        q2[0] = pack2(a.x * c,  a.y * c);   q2[1] = pack2(a.z * c,  a.w * c);
        q2[2] = pack2(b4.x * c, b4.y * c);  q2[3] = pack2(b4.z * c, b4.w * c);
        q2[4] = pack2(cc.x * c, cc.y * c);  q2[5] = pack2(cc.z * c, cc.w * c);
        q2[6] = pack2(d4.x * c, d4.y * c);  q2[7] = pack2(d4.z * c, d4.w * c);
    }
    __syncthreads();

    // ---- pass 1: z sums ----
    float zp = 0.f, zn = 0.f;
    for (int k = warp; k < nk; k += 8) {
        const float4* kr = (const float4*)(sk + k * 16);
        float4 kA = kr[0], kB = kr[1], kC = kr[2], kD = kr[3];
        u64 dot2 = 0ull;
        ffma2(dot2, q2[0], pack2(kA.x, kA.y), dot2);
        ffma2(dot2, q2[1], pack2(kA.z, kA.w), dot2);
        ffma2(dot2, q2[2], pack2(kB.x, kB.y), dot2);
        ffma2(dot2, q2[3], pack2(kB.z, kB.w), dot2);
        ffma2(dot2, q2[4], pack2(kC.x, kC.y), dot2);
        ffma2(dot2, q2[5], pack2(kC.z, kC.w), dot2);
        ffma2(dot2, q2[6], pack2(kD.x, kD.y), dot2);
        ffma2(dot2, q2[7], pack2(kD.z, kD.w), dot2);
        float dlo, dhi; unpack2(dot2, dlo, dhi);
        float dot = dlo + dhi;
        zp += ex2(dot);
        zn += ex2(-dot);
    }
    zpart[warp][0][lane] = zp;
    zpart[warp][1][lane] = zn;
    __syncthreads();

    // everyone computes its lane-query's izp/izn
    float izp = 0.f, izn = 0.f;
    {
        float szp = 0.f, szn = 0.f;
#pragma unroll
        for (int w = 0; w < 8; w++) { szp += zpart[w][0][lane]; szn += zpart[w][1][lane]; }
        izp = __frcp_rn(szp);
        izn = __frcp_rn(szn);
    }

    // ---- pass 2: combined accumulation ----
    u64 acc2[8];
#pragma unroll
    for (int i = 0; i < 8; i++) acc2[i] = 0ull;
    for (int k = warp; k < nk; k += 8) {
        const float4* kr = (const float4*)(sk + k * 16);
        float4 kA = kr[0], kB = kr[1], kC = kr[2], kD = kr[3];
        u64 dot2 = 0ull;
        ffma2(dot2, q2[0], pack2(kA.x, kA.y), dot2);
        ffma2(dot2, q2[1], pack2(kA.z, kA.w), dot2);
        ffma2(dot2, q2[2], pack2(kB.x, kB.y), dot2);
        ffma2(dot2, q2[3], pack2(kB.z, kB.w), dot2);
        ffma2(dot2, q2[4], pack2(kC.x, kC.y), dot2);
        ffma2(dot2, q2[5], pack2(kC.z, kC.w), dot2);
        ffma2(dot2, q2[6], pack2(kD.x, kD.y), dot2);
        ffma2(dot2, q2[7], pack2(kD.z, kD.w), dot2);
        float dlo, dhi; unpack2(dot2, dlo, dhi);
        float dot = dlo + dhi;
        float w = ex2(dot) * izp - ex2(-dot) * izn;
        u64 w2 = pack2(w, w);
        ffma2(acc2[0], pack2(kA.x, kA.y), w2, acc2[0]);
        ffma2(acc2[1], pack2(kA.z, kA.w), w2, acc2[1]);
        ffma2(acc2[2], pack2(kB.x, kB.y), w2, acc2[2]);
        ffma2(acc2[3], pack2(kB.z, kB.w), w2, acc2[3]);
        ffma2(acc2[4], pack2(kC.x, kC.y), w2, acc2[4]);
        ffma2(acc2[5], pack2(kC.z, kC.w), w2, acc2[5]);
        ffma2(acc2[6], pack2(kD.x, kD.y), w2, acc2[6]);
        ffma2(acc2[7], pack2(kD.z, kD.w), w2, acc2[7]);
    }
    __syncthreads();   // all key reads done; safe to reuse sk

    // dump acc partials: [warp][d][lane]
    {
        float* pw = sk + warp * (16 * 32);
#pragma unroll
        for (int i = 0; i < 8; i++) {
            float lo, hi; unpack2(acc2[i], lo, hi);
            pw[(2 * i) * 32 + lane]     = lo;
            pw[(2 * i + 1) * 32 + lane] = hi;
        }
    }
    __syncthreads();

    // merge 8 warps into warp-0 region
    for (int i = tid; i < 16 * 32; i += 256) {
        float s = sk[i];
#pragma unroll
        for (int w = 1; w < 8; w++) s += sk[w * (16 * 32) + i];
        sk[i] = s;
    }
    __syncthreads();

    // finalize: thread = query row
    if (tid < 32) {
        float x[16];
        if (nk > 0) {
#pragma unroll
            for (int d = 0; d < 16; d++) x[d] = sk[d * 32 + tid];
        } else {
#pragma unroll
            for (int d = 0; d < 16; d++) x[d] = 0.f;
        }
        const float4* q4 = (const float4*)(qb + (size_t)tid * Dc);
        float4 a = q4[0], b4 = q4[1], cc = q4[2], d4 = q4[3];
        float qq[16] = {a.x,a.y,a.z,a.w,b4.x,b4.y,b4.z,b4.w,
                        cc.x,cc.y,cc.z,cc.w,d4.x,d4.y,d4.z,d4.w};
        float ss = 0.f;
#pragma unroll
        for (int d = 0; d < 16; d++) { x[d] += qq[d]; ss += x[d] * x[d]; }
        float r = rsqrtf(ss * 0.0625f + EPSc);
#pragma unroll
        for (int d = 0; d < 16; d++) x[d] = x[d] * r * attn_nw[d];

        const float u00 = up_w[6*hh+0], u01 = up_w[6*hh+1], u02 = up_w[6*hh+2];
        const float u10 = up_w[6*hh+3], u11 = up_w[6*hh+4], u12 = up_w[6*hh+5];
        const float dw0 = down_w[2*hh+0], dw1 = down_w[2*hh+1];

        float v[16];
        ss = 0.f;
#pragma unroll
        for (int d = 0; d < 16; d++) {
            float xm2 = (d >= 2) ? x[d-2] : 0.f;
            float xm1 = (d >= 1) ? x[d-1] : 0.f;
            float m0 = u00 * xm2 + u01 * xm1 + u02 * x[d];
            float m1 = u10 * xm2 + u11 * xm1 + u12 * x[d];
            float y  = dw0 * gelu_exact(m0) + dw1 * gelu_exact(m1);
            v[d] = x[d] + y;
            ss += v[d] * v[d];
        }
        r = rsqrtf(ss * 0.0625f + EPSc);
        float nv[16];
#pragma unroll
        for (int d = 0; d < 16; d++) nv[d] = v[d] * r * ffn_nw[d];
        float4* orow = (float4*)(out + ((size_t)((b * Hc + hh) * Lc + p * Nc + tid)) * Dc);
        orow[0] = make_float4(nv[0],  nv[1],  nv[2],  nv[3]);
        orow[1] = make_float4(nv[4],  nv[5],  nv[6],  nv[7]);
        orow[2] = make_float4(nv[8],  nv[9],  nv[10], nv[11]);
        orow[3] = make_float4(nv[12], nv[13], nv[14], nv[15]);
    }
}

// ---------------------------------------------------------------------------
__global__ __launch_bounds__(512) void final_copy_kernel(
    const float* __restrict__ hbuf,
    const float* __restrict__ mix_w, const float* __restrict__ mix_b,
    const float* __restrict__ fore_w, const float* __restrict__ fore_b,
    const float* __restrict__ x_original,
    float* __restrict__ out)
{
    const int t = threadIdx.x;
    if (blockIdx.z == 1) {
        int idx = (blockIdx.y * Nc + blockIdx.x) * 512 + t;
        if (idx < (Bc * SEQc * Nc) / 4)
            ((float4*)(out + Bc * PREDc * Nc))[idx] = ((const float4*)x_original)[idx];
        return;
    }

    __shared__ float hm[16 * 32];
    const int n = blockIdx.x, b = blockIdx.y;
    const int d = t >> 5, p = t & 31;

    float acc = mix_b[0];
#pragma unroll
    for (int h = 0; h < Hc; h++)
        acc += hbuf[((size_t)((b * Hc + h) * Lc + p * Nc + n)) * Dc + d] * mix_w[h];
    hm[d * 32 + p] = acc;
    __syncthreads();

    if (t < PREDc) {
        int dd = t / NFc, f = t - dd * NFc;
        float v = fore_b[f];
#pragma unroll
        for (int pp = 0; pp < Pc; pp++)
            v += hm[dd * 32 + pp] * fore_w[f * Pc + pp];
        out[((size_t)b * PREDc + t) * Nc + n] = v;
    }
}

// ---------------------------------------------------------------------------
extern "C" void kernel_launch(void* const* d_in, const int* in_sizes, int n_in,
                              void* d_out, int out_size)
{
    const float* tokens     = (const float*)d_in[0];
    const float* x_original = (const float*)d_in[1];
    const float* log_scales = (const float*)d_in[2];
    const float* attn_norm  = (const float*)d_in[3];
    const float* conv_up    = (const float*)d_in[4];
    const float* conv_down  = (const float*)d_in[5];
    const float* ffn_norm   = (const float*)d_in[6];
    const float* mix_w      = (const float*)d_in[7];
    const float* mix_b      = (const float*)d_in[8];
    const float* fore_w     = (const float*)d_in[9];
    const float* fore_b     = (const float*)d_in[10];
    float* out = (float*)d_out;

    float *h0, *h1;
    cudaGetSymbolAddress((void**)&h0, g_h0);
    cudaGetSymbolAddress((void**)&h1, g_h1);

    dim3 ag(Pc, Hc, Bc);

    attn_ffn_kernel<<<ag, 256>>>(tokens, h0, log_scales + 0, attn_norm + 0,
                                 conv_up + 0, conv_down + 0, ffn_norm + 0);
    attn_ffn_kernel<<<ag, 256>>>(h0, h1, log_scales + 1, attn_norm + Dc,
                                 conv_up + 2*Hc*3, conv_down + Hc*2, ffn_norm + Dc);

    const int fc = Bc * PREDc * Nc;   // 12288
    const int xo = Bc * SEQc * Nc;    // 65536
    dim3 fg(Nc, Bc, (out_size >= fc + xo) ? 2 : 1);
    final_copy_kernel<<<fg, 512>>>(h1, mix_w, mix_b, fore_w, fore_b, x_original, out);
}